// round 11
// baseline (speedup 1.0000x reference)
#include <cuda_runtime.h>
#include <math.h>

#define Bc 8
#define Nc 196
#define Dc 512
#define Mc 20
#define Kc 77
#define Hc 8
#define Rr (Bc*Nc)
#define RT (Rr*Kc)
#define QS_ELEMS (Bc*Nc*Dc*Mc)
#define KKEEP 51u

typedef unsigned int uint;
typedef unsigned long long ull;

__device__ __align__(16) float g_qin [Kc*Dc];
__device__ __align__(16) float g_kin [Rr*Dc];
__device__ __align__(16) float g_q   [Kc*Dc];
__device__ __align__(16) float g_k   [Rr*Dc];
__device__ __align__(16) float g_v   [Rr*Dc];
__device__ __align__(16) float g_attn[Bc*Hc*Kc*Nc];
__device__ __align__(16) float g_ctx [Bc*Kc*Dc];
__device__ __align__(16) float g_A   [Bc*Kc*Dc];
__device__ __align__(16) float g_w   [Rr*Kc];
__device__ __align__(16) float g_S   [Rr*Dc];
__device__ __align__(16) float g_H   [(size_t)RT*Dc];
__device__ __align__(16) float g_Qp  [Rr*Mc];

static __device__ __forceinline__ ull pk2(float lo, float hi){
    ull r; asm("mov.b64 %0, {%1, %2};" : "=l"(r) : "f"(lo), "f"(hi)); return r;
}
static __device__ __forceinline__ void ffma2(ull &d, ull a, ull b){
    asm("fma.rn.f32x2 %0, %1, %2, %0;" : "+l"(d) : "l"(a), "l"(b));
}
static __device__ __forceinline__ void upk2(ull v, float &lo, float &hi){
    asm("mov.b64 {%0, %1}, %2;" : "=f"(lo), "=f"(hi) : "l"(v));
}
static __device__ __forceinline__ float gelu_exact(float x){
    return 0.5f * x * (1.0f + erff(x * 0.70710678118654752f));
}

// ---------- LayerNorm ----------
__global__ void ln_kernel(const float* __restrict__ in, float* __restrict__ out,
                          const float* __restrict__ gg, const float* __restrict__ bb){
    int row = blockIdx.x, t = threadIdx.x;
    float4 x = reinterpret_cast<const float4*>(in + (size_t)row*Dc)[t];
    float s = x.x+x.y+x.z+x.w;
    float q = x.x*x.x+x.y*x.y+x.z*x.z+x.w*x.w;
    #pragma unroll
    for (int o=16;o;o>>=1){ s += __shfl_xor_sync(0xffffffffu,s,o); q += __shfl_xor_sync(0xffffffffu,q,o); }
    __shared__ float ws[4], wq[4];
    if ((t&31)==0){ ws[t>>5]=s; wq[t>>5]=q; }
    __syncthreads();
    s = ws[0]+ws[1]+ws[2]+ws[3]; q = wq[0]+wq[1]+wq[2]+wq[3];
    float mu = s*(1.f/512.f);
    float rstd = rsqrtf(q*(1.f/512.f) - mu*mu + 1e-5f);
    float4 g4 = reinterpret_cast<const float4*>(gg)[t];
    float4 b4 = reinterpret_cast<const float4*>(bb)[t];
    float4 y;
    y.x=(x.x-mu)*rstd*g4.x+b4.x; y.y=(x.y-mu)*rstd*g4.y+b4.y;
    y.z=(x.z-mu)*rstd*g4.z+b4.z; y.w=(x.w-mu)*rstd*g4.w+b4.w;
    reinterpret_cast<float4*>(out + (size_t)row*Dc)[t] = y;
}

// ---------- small SGEMM ----------
static __device__ __forceinline__
void sgemm_body(const float* __restrict__ A, const float* __restrict__ W,
                const float* __restrict__ bias, float* __restrict__ C, int Mrows){
    __shared__ float As[32][132];
    __shared__ float Bs[32][132];
    int t = threadIdx.x;
    int tx = t & 15, ty = t >> 4;
    int n0 = blockIdx.x * 128;
    int m0 = blockIdx.y * 128;
    ull acc[8][4];
    #pragma unroll
    for (int i=0;i<8;i++)
        #pragma unroll
        for (int j=0;j<4;j++) acc[i][j]=0ull;
    int la_r = t >> 3, la_c = (t & 7) * 4;
    for (int k0=0;k0<512;k0+=32){
        #pragma unroll
        for (int p=0;p<4;p++){
            int row = la_r + p*32;
            int gr = m0 + row;
            float4 va = make_float4(0.f,0.f,0.f,0.f);
            if (gr < Mrows) va = *reinterpret_cast<const float4*>(&A[(size_t)gr*512 + k0 + la_c]);
            As[la_c+0][row]=va.x; As[la_c+1][row]=va.y; As[la_c+2][row]=va.z; As[la_c+3][row]=va.w;
            float4 vb = *reinterpret_cast<const float4*>(&W[(size_t)(n0+row)*512 + k0 + la_c]);
            Bs[la_c+0][row]=vb.x; Bs[la_c+1][row]=vb.y; Bs[la_c+2][row]=vb.z; Bs[la_c+3][row]=vb.w;
        }
        __syncthreads();
        #pragma unroll
        for (int kk=0;kk<32;kk++){
            float4 a0 = *reinterpret_cast<const float4*>(&As[kk][ty*8]);
            float4 a1 = *reinterpret_cast<const float4*>(&As[kk][ty*8+4]);
            float4 b0 = *reinterpret_cast<const float4*>(&Bs[kk][tx*8]);
            float4 b1 = *reinterpret_cast<const float4*>(&Bs[kk][tx*8+4]);
            ull bp0=pk2(b0.x,b0.y), bp1=pk2(b0.z,b0.w), bp2=pk2(b1.x,b1.y), bp3=pk2(b1.z,b1.w);
            float av[8]={a0.x,a0.y,a0.z,a0.w,a1.x,a1.y,a1.z,a1.w};
            #pragma unroll
            for (int i=0;i<8;i++){
                ull ad = pk2(av[i], av[i]);
                ffma2(acc[i][0], ad, bp0); ffma2(acc[i][1], ad, bp1);
                ffma2(acc[i][2], ad, bp2); ffma2(acc[i][3], ad, bp3);
            }
        }
        __syncthreads();
    }
    #pragma unroll
    for (int i=0;i<8;i++){
        int row = m0 + ty*8 + i;
        if (row >= Mrows) continue;
        float* cp = &C[(size_t)row*512 + n0 + tx*8];
        const float* bp = &bias[n0 + tx*8];
        #pragma unroll
        for (int j=0;j<4;j++){
            float lo,hi; upk2(acc[i][j], lo, hi);
            cp[2*j] = lo + bp[2*j]; cp[2*j+1] = hi + bp[2*j+1];
        }
    }
}

__global__ __launch_bounds__(256)
void sgemm_nt(const float* __restrict__ A, const float* __restrict__ W,
              const float* __restrict__ bias, float* __restrict__ C, int Mrows){
    sgemm_body(A, W, bias, C, Mrows);
}

__global__ __launch_bounds__(256)
void sgemm_qkv(const float* __restrict__ F, const float* __restrict__ ipw,
               const float* __restrict__ ipb){
    int z = blockIdx.z;
    if (z == 0){ sgemm_body(g_kin, ipw + 512*512, ipb + 512, g_k, Rr); }
    else if (z == 1){ sgemm_body(F, ipw + 2*512*512, ipb + 1024, g_v, Rr); }
    else { if (blockIdx.y) return; sgemm_body(g_qin, ipw, ipb, g_q, Kc); }
}

// ---------- big GEMM: 16x8 microtile, 128 threads, dup-pair A smem ----------
// A plane: 32 kcols x 288 floats (64 granules of 16B + pad per 8); B: 32 x 132
#define GA_STR 288
#define GB_SMEM ((32*GA_STR + 32*132)*4)

__global__ __launch_bounds__(128, 2)
void gemm_big(const float* __restrict__ F, const float* __restrict__ w1,
              const float* __restrict__ b1){
    extern __shared__ float dsm[];
    float* As2 = dsm;                 // 32 * 288
    float* Bsf = dsm + 32*GA_STR;     // 32 * 132
    int t = threadIdx.x;              // 128
    int tx = t & 15, ty = t >> 4;     // ty 0..7
    int n0 = blockIdx.x * 128;
    int m0 = blockIdx.y * 128;
    int la_r = t >> 3;                // 0..15
    int la_c = (t & 7) * 4;
    int sA = t & 7;                   // kcol>>2 for this thread's 4 kcols

    int offF[8], offA[8];
    float wv[8];
    uint okm = 0;
    #pragma unroll
    for (int p=0;p<8;p++){
        int gr = m0 + la_r + 16*p;
        bool ok = gr < RT;
        int grc = ok ? gr : 0;
        int rn = grc / 77;
        int k  = grc - rn*77;
        int b  = rn / 196;
        offF[p] = rn*512;
        offA[p] = (b*77 + k)*512;
        wv[p] = g_w[rn*77 + k];
        okm |= (ok ? 1u : 0u) << p;
    }

    ull acc[16][4];
    #pragma unroll
    for (int i=0;i<16;i++)
        #pragma unroll
        for (int j=0;j<4;j++) acc[i][j]=0ull;

    for (int c = 0; c < 16; c++){
        int k0 = c * 32;
        #pragma unroll
        for (int p=0;p<8;p++){
            int r = la_r + 16*p;
            float4 F4 = *reinterpret_cast<const float4*>(F   + offF[p] + k0 + la_c);
            float4 A4 = *reinterpret_cast<const float4*>(g_A + offA[p] + k0 + la_c);
            float4 S4 = *reinterpret_cast<const float4*>(g_S + offF[p] + k0 + la_c);
            float4 x4;
            if (okm & (1u<<p)){
                float wq = wv[p];
                x4.x = F4.x*(wq*A4.x - S4.x); x4.y = F4.y*(wq*A4.y - S4.y);
                x4.z = F4.z*(wq*A4.z - S4.z); x4.w = F4.w*(wq*A4.w - S4.w);
            } else x4 = make_float4(0.f,0.f,0.f,0.f);
            int gst = (r >> 1) ^ sA;                    // storage granule
            int base = 4*gst + 4*(gst>>3) + (r & 1)*2;  // padded offset
            *reinterpret_cast<float2*>(&As2[(la_c+0)*GA_STR + base]) = make_float2(x4.x, x4.x);
            *reinterpret_cast<float2*>(&As2[(la_c+1)*GA_STR + base]) = make_float2(x4.y, x4.y);
            *reinterpret_cast<float2*>(&As2[(la_c+2)*GA_STR + base]) = make_float2(x4.z, x4.z);
            *reinterpret_cast<float2*>(&As2[(la_c+3)*GA_STR + base]) = make_float2(x4.w, x4.w);
            float4 vb = *reinterpret_cast<const float4*>(&w1[(size_t)(n0 + r)*512 + k0 + la_c]);
            Bsf[(la_c+0)*132 + r] = vb.x; Bsf[(la_c+1)*132 + r] = vb.y;
            Bsf[(la_c+2)*132 + r] = vb.z; Bsf[(la_c+3)*132 + r] = vb.w;
        }
        __syncthreads();
        #pragma unroll 4
        for (int kk=0;kk<32;kk++){
            int sK = kk >> 2;
            const float* ap = &As2[kk*GA_STR + 36*ty];
            ull ad[16];
            #pragma unroll
            for (int j=0;j<8;j++){
                ulonglong2 u = *reinterpret_cast<const ulonglong2*>(ap + 4*(j ^ sK));
                ad[2*j] = u.x; ad[2*j+1] = u.y;
            }
            ulonglong2 b0 = *reinterpret_cast<const ulonglong2*>(&Bsf[kk*132 + tx*8]);
            ulonglong2 b1v = *reinterpret_cast<const ulonglong2*>(&Bsf[kk*132 + tx*8 + 4]);
            ull bp0 = b0.x, bp1 = b0.y, bp2 = b1v.x, bp3 = b1v.y;
            #pragma unroll
            for (int i=0;i<16;i++){
                ffma2(acc[i][0], ad[i], bp0); ffma2(acc[i][1], ad[i], bp1);
                ffma2(acc[i][2], ad[i], bp2); ffma2(acc[i][3], ad[i], bp3);
            }
        }
        __syncthreads();
    }

    #pragma unroll
    for (int i=0;i<16;i++){
        int row = m0 + ty*16 + i;
        if (row >= RT) continue;
        float* cp = &g_H[(size_t)row*512 + n0 + tx*8];
        const float* bp = &b1[n0 + tx*8];
        #pragma unroll
        for (int j=0;j<4;j++){
            float lo,hi; upk2(acc[i][j], lo, hi);
            cp[2*j] = lo + bp[2*j]; cp[2*j+1] = hi + bp[2*j+1];
        }
    }
}

// ---------- attention (ctx 4-way parallel) ----------
__global__ void attn_kernel(){
    int kq = blockIdx.x, h = blockIdx.y, b = blockIdx.z;
    int t = threadIdx.x;
    __shared__ float sq[64];
    __shared__ float sc[196];
    __shared__ float red[8];
    __shared__ float ctxred[4][64];
    if (t < 64) sq[t] = g_q[kq*512 + h*64 + t];
    __syncthreads();
    float val = -1e30f;
    if (t < 196){
        const float* kr = &g_k[((size_t)(b*196 + t))*512 + h*64];
        float s = 0.f;
        #pragma unroll
        for (int d=0; d<64; d+=4){
            float4 k4 = *reinterpret_cast<const float4*>(&kr[d]);
            s += sq[d]*k4.x + sq[d+1]*k4.y + sq[d+2]*k4.z + sq[d+3]*k4.w;
        }
        val = s * 0.125f;
    }
    float mv = val;
    #pragma unroll
    for (int o=16;o;o>>=1) mv = fmaxf(mv, __shfl_xor_sync(0xffffffffu, mv, o));
    if ((t&31)==0) red[t>>5] = mv;
    __syncthreads();
    float rm = red[0];
    #pragma unroll
    for (int i=1;i<8;i++) rm = fmaxf(rm, red[i]);
    float e = (t<196) ? expf(val - rm) : 0.f;
    float se = e;
    #pragma unroll
    for (int o=16;o;o>>=1) se += __shfl_xor_sync(0xffffffffu, se, o);
    __syncthreads();
    if ((t&31)==0) red[t>>5] = se;
    __syncthreads();
    float tot = red[0]+red[1]+red[2]+red[3]+red[4]+red[5]+red[6]+red[7];
    float a = e / tot;
    if (t < 196){
        sc[t] = a;
        g_attn[(((size_t)(b*Hc+h))*Kc + kq)*Nc + t] = a;
    }
    __syncthreads();
    {
        int g = t >> 6, d = t & 63;
        const float* vb = &g_v[((size_t)(b*196))*512 + h*64 + d];
        float acc = 0.f;
        for (int n = g; n < 196; n += 4) acc += sc[n]*vb[(size_t)n*512];
        ctxred[g][d] = acc;
    }
    __syncthreads();
    if (t < 64){
        float r = ctxred[0][t]+ctxred[1][t]+ctxred[2][t]+ctxred[3][t];
        g_ctx[((size_t)(b*Kc)+kq)*512 + h*64 + t] = r;
    }
}

__global__ void aw_kernel(float* __restrict__ out_aw){
    int k = blockIdx.x, b = blockIdx.y;
    int n = threadIdx.x;
    if (n < 196){
        float s = 0.f;
        #pragma unroll
        for (int h=0;h<8;h++) s += g_attn[(((size_t)(b*Hc+h))*Kc + k)*Nc + n];
        s *= 0.125f;
        out_aw[((size_t)(b*Kc)+k)*Nc + n] = s;
        g_w[((size_t)(b*196+n))*Kc + k] = s;
    }
}

__global__ void sbar_kernel(){
    int r = blockIdx.x;
    int b = r / 196;
    int t = threadIdx.x;
    __shared__ float ws[Kc];
    for (int i=t;i<Kc;i+=128) ws[i] = g_w[(size_t)r*Kc + i];
    __syncthreads();
    float4 acc = make_float4(0.f,0.f,0.f,0.f);
    const float4* Ab = reinterpret_cast<const float4*>(&g_A[(size_t)b*Kc*512]);
    for (int k=0;k<Kc;k++){
        float wv = ws[k];
        float4 a4 = Ab[(size_t)k*128 + t];
        acc.x += wv*a4.x; acc.y += wv*a4.y; acc.z += wv*a4.z; acc.w += wv*a4.w;
    }
    float inv = 1.0f/77.0f;
    acc.x*=inv; acc.y*=inv; acc.z*=inv; acc.w*=inv;
    reinterpret_cast<float4*>(&g_S[(size_t)r*512])[t] = acc;
}

// ---------- H -> Qp ----------
__global__ __launch_bounds__(640)
void h2qp(const float* __restrict__ w2, const float* __restrict__ b2,
          const float* __restrict__ lng, const float* __restrict__ lnb){
    int rn = blockIdx.x;
    int t = threadIdx.x;
    int wid = t >> 5, lane = t & 31;
    __shared__ float sW[Mc*512];
    __shared__ float sg[512], sb[512];
    __shared__ float ws[80];
    __shared__ float sacc[Mc*Mc];
    for (int i=t;i<2560;i+=640) reinterpret_cast<float4*>(sW)[i] = reinterpret_cast<const float4*>(w2)[i];
    for (int i=t;i<128;i+=640){
        reinterpret_cast<float4*>(sg)[i] = reinterpret_cast<const float4*>(lng)[i];
        reinterpret_cast<float4*>(sb)[i] = reinterpret_cast<const float4*>(lnb)[i];
    }
    if (t < 77) ws[t] = g_w[(size_t)rn*77 + t];
    __syncthreads();
    float wsum = 0.f;
    #pragma unroll 7
    for (int k=0;k<77;k++) wsum += ws[k];

    float accL[Mc];
    #pragma unroll
    for (int m=0;m<Mc;m++) accL[m] = 0.f;

    for (int k = wid; k < 77; k += 20){
        const float* hp = &g_H[((size_t)rn*77 + k)*512];
        float4 h4[4];
        #pragma unroll
        for (int i=0;i<4;i++) h4[i] = *reinterpret_cast<const float4*>(&hp[128*i + lane*4]);
        float s = 0.f, q = 0.f;
        #pragma unroll
        for (int i=0;i<4;i++){
            s += h4[i].x + h4[i].y + h4[i].z + h4[i].w;
            q += h4[i].x*h4[i].x + h4[i].y*h4[i].y + h4[i].z*h4[i].z + h4[i].w*h4[i].w;
        }
        #pragma unroll
        for (int o=16;o;o>>=1){
            s += __shfl_xor_sync(0xffffffffu, s, o);
            q += __shfl_xor_sync(0xffffffffu, q, o);
        }
        float mu = s*(1.f/512.f);
        float rstd = rsqrtf(q*(1.f/512.f) - mu*mu + 1e-5f);
        float y[16];
        #pragma unroll
        for (int i=0;i<4;i++){
            int col = 128*i + lane*4;
            y[4*i+0] = gelu_exact((h4[i].x - mu)*rstd*sg[col+0] + sb[col+0]);
            y[4*i+1] = gelu_exact((h4[i].y - mu)*rstd*sg[col+1] + sb[col+1]);
            y[4*i+2] = gelu_exact((h4[i].z - mu)*rstd*sg[col+2] + sb[col+2]);
            y[4*i+3] = gelu_exact((h4[i].w - mu)*rstd*sg[col+3] + sb[col+3]);
        }
        float wk = ws[k];
        #pragma unroll
        for (int m=0;m<Mc;m++){
            const float4* wm = reinterpret_cast<const float4*>(&sW[m*512]);
            float d = 0.f;
            #pragma unroll
            for (int i=0;i<4;i++){
                float4 c4 = wm[32*i + lane];
                d += y[4*i]*c4.x + y[4*i+1]*c4.y + y[4*i+2]*c4.z + y[4*i+3]*c4.w;
            }
            accL[m] += wk*d;
        }
    }
    #pragma unroll
    for (int m=0;m<Mc;m++){
        float a = accL[m];
        #pragma unroll
        for (int o=16;o;o>>=1) a += __shfl_xor_sync(0xffffffffu, a, o);
        if (lane == 0) sacc[wid*Mc + m] = a;
    }
    __syncthreads();
    if (t < Mc){
        float a = 0.f;
        #pragma unroll
        for (int w2i=0;w2i<Mc;w2i++) a += sacc[w2i*Mc + t];
        g_Qp[(size_t)rn*Mc + t] = a + b2[t]*wsum;
    }
}

// ---------- top-51 + normalize + output ----------
__global__ void topk_kernel(const float* __restrict__ F, const float* __restrict__ T,
                            float* __restrict__ out){
    int r = blockIdx.x;
    int m = blockIdx.y;
    int t = threadIdx.x;
    __shared__ uint hist[256];
    __shared__ uint sh_pref, sh_rem;
    __shared__ uint wsum[4];
    __shared__ uint wtot[4];
    __shared__ float sred[4];

    float Qp = g_Qp[(size_t)r*Mc + m];
    float4 F4 = reinterpret_cast<const float4*>(&F[(size_t)r*512])[t];
    float4 T4 = reinterpret_cast<const float4*>(&T[(size_t)m*512])[t];
    float q0=F4.x*T4.x, q1=F4.y*T4.y, q2=F4.z*T4.z, q3=F4.w*T4.w;
    uint k0=__float_as_uint(fabsf(q0)), k1=__float_as_uint(fabsf(q1));
    uint k2=__float_as_uint(fabsf(q2)), k3=__float_as_uint(fabsf(q3));

    uint lane = t & 31, wid = t >> 5;
    uint pref = 0, hmask = 0, rem = KKEEP;
    for (int bp=3; bp>=0; bp--){
        hist[t] = 0; hist[t+128] = 0;
        __syncthreads();
        uint bm = hmask, p = pref;
        if ((k0 & bm) == p) atomicAdd(&hist[(k0 >> (bp*8)) & 255u], 1u);
        if ((k1 & bm) == p) atomicAdd(&hist[(k1 >> (bp*8)) & 255u], 1u);
        if ((k2 & bm) == p) atomicAdd(&hist[(k2 >> (bp*8)) & 255u], 1u);
        if ((k3 & bm) == p) atomicAdd(&hist[(k3 >> (bp*8)) & 255u], 1u);
        __syncthreads();
        uint h_lo = hist[2*t], h_hi = hist[2*t+1];
        uint pairv = h_lo + h_hi;
        uint v = pairv;
        #pragma unroll
        for (int o=1;o<32;o<<=1){
            uint u = __shfl_down_sync(0xffffffffu, v, o);
            if (lane < 32-o) v += u;
        }
        if (lane == 0) wtot[wid] = v;
        __syncthreads();
        uint tail = 0;
        for (uint wq = wid+1; wq < 4; wq++) tail += wtot[wq];
        uint Spair = v + tail;
        uint S0 = Spair;
        uint S1 = Spair - h_lo;
        uint S2 = Spair - pairv;
        if (S1 >= rem && S2 < rem){
            sh_pref = pref | ((uint)(2*t+1) << (bp*8));
            sh_rem = rem - S2;
        }
        if (S0 >= rem && S1 < rem){
            sh_pref = pref | ((uint)(2*t) << (bp*8));
            sh_rem = rem - S1;
        }
        __syncthreads();
        pref = sh_pref; rem = sh_rem;
        hmask |= (255u << (bp*8));
        __syncthreads();
    }
    uint thr = pref, req = rem;

    uint e0 = (k0==thr), e1 = (k1==thr), e2 = (k2==thr), e3 = (k3==thr);
    uint tc = e0+e1+e2+e3;
    uint inc = tc;
    #pragma unroll
    for (int o=1;o<32;o<<=1){
        uint v = __shfl_up_sync(0xffffffffu, inc, o);
        if (lane >= o) inc += v;
    }
    if (lane == 31) wsum[wid] = inc;
    __syncthreads();
    uint woff = 0;
    for (uint i=0;i<wid;i++) woff += wsum[i];
    uint p0 = woff + inc - tc;
    uint p1 = p0 + e0, p2 = p1 + e1, p3 = p2 + e2;
    bool s0 = (k0 > thr) || (e0 && p0 < req);
    bool s1 = (k1 > thr) || (e1 && p1 < req);
    bool s2 = (k2 > thr) || (e2 && p2 < req);
    bool s3 = (k3 > thr) || (e3 && p3 < req);

    float v0 = Qp*q0, v1 = Qp*q1, v2 = Qp*q2, v3 = Qp*q3;
    float ss = (s0?v0*v0:0.f) + (s1?v1*v1:0.f) + (s2?v2*v2:0.f) + (s3?v3*v3:0.f);
    #pragma unroll
    for (int o=16;o;o>>=1) ss += __shfl_xor_sync(0xffffffffu, ss, o);
    if (lane == 0) sred[wid] = ss;
    __syncthreads();
    float tot = sred[0]+sred[1]+sred[2]+sred[3];
    float nrm = fmaxf(sqrtf(tot), 1e-6f);
    float invn = 1.0f / nrm;

    size_t base = ((size_t)r*512 + (size_t)t*4)*Mc + m;
    out[base       ] = s0 ? v0*invn : 0.f;
    out[base +   Mc] = s1 ? v1*invn : 0.f;
    out[base + 2*Mc] = s2 ? v2*invn : 0.f;
    out[base + 3*Mc] = s3 ? v3*invn : 0.f;
}

// ---------- launch ----------
extern "C" void kernel_launch(void* const* d_in, const int* in_sizes, int n_in,
                              void* d_out, int out_size){
    const float* F    = (const float*)d_in[0];
    const float* text = (const float*)d_in[1];
    const float* ipw  = (const float*)d_in[2];
    const float* ipb  = (const float*)d_in[3];
    const float* outw = (const float*)d_in[4];
    const float* outb = (const float*)d_in[5];
    const float* ln1g = (const float*)d_in[6];
    const float* ln1b = (const float*)d_in[7];
    const float* ln2g = (const float*)d_in[8];
    const float* ln2b = (const float*)d_in[9];
    const float* w1   = (const float*)d_in[10];
    const float* b1   = (const float*)d_in[11];
    const float* mlng = (const float*)d_in[12];
    const float* mlnb = (const float*)d_in[13];
    const float* w2   = (const float*)d_in[14];
    const float* b2   = (const float*)d_in[15];
    const float* tmpl = (const float*)d_in[16];
    float* out = (float*)d_out;

    float *p_qin, *p_kin, *p_ctx, *p_A;
    cudaGetSymbolAddress((void**)&p_qin, g_qin);
    cudaGetSymbolAddress((void**)&p_kin, g_kin);
    cudaGetSymbolAddress((void**)&p_ctx, g_ctx);
    cudaGetSymbolAddress((void**)&p_A,   g_A);

    cudaFuncSetAttribute(gemm_big, cudaFuncAttributeMaxDynamicSharedMemorySize, GB_SMEM);

    ln_kernel<<<Kc, 128>>>(text, p_qin, ln1g, ln1b);
    ln_kernel<<<Rr, 128>>>(F, p_kin, ln1g, ln1b);

    sgemm_qkv<<<dim3(4,13,3), 256>>>(F, ipw, ipb);

    attn_kernel<<<dim3(Kc, Hc, Bc), 256>>>();
    aw_kernel<<<dim3(Kc, Bc), 224>>>(out + QS_ELEMS);

    sgemm_nt<<<dim3(4,5), 256>>>(p_ctx, outw, outb, p_A, Bc*Kc);
    ln_kernel<<<Bc*Kc, 128>>>(p_A, p_A, ln2g, ln2b);

    sbar_kernel<<<Rr, 128>>>();

    gemm_big<<<dim3(4, (RT + 127)/128), 128, GB_SMEM>>>(F, w1, b1);

    h2qp<<<Rr, 640>>>(w2, b2, mlng, mlnb);

    topk_kernel<<<dim3(Rr, Mc), 128>>>(F, tmpl, out);
}

// round 12
// speedup vs baseline: 1.1247x; 1.1247x over previous
#include <cuda_runtime.h>
#include <math.h>

#define Bc 8
#define Nc 196
#define Dc 512
#define Mc 20
#define Kc 77
#define Hc 8
#define Rr (Bc*Nc)
#define RT (Rr*Kc)
#define QS_ELEMS (Bc*Nc*Dc*Mc)
#define KKEEP 51u

typedef unsigned int uint;
typedef unsigned long long ull;

__device__ __align__(16) float g_qin [Kc*Dc];
__device__ __align__(16) float g_kin [Rr*Dc];
__device__ __align__(16) float g_q   [Kc*Dc];
__device__ __align__(16) float g_k   [Rr*Dc];
__device__ __align__(16) float g_v   [Rr*Dc];
__device__ __align__(16) float g_attn[Bc*Hc*Kc*Nc];
__device__ __align__(16) float g_ctx [Bc*Kc*Dc];
__device__ __align__(16) float g_A   [Bc*Kc*Dc];
__device__ __align__(16) float g_w   [Rr*Kc];
__device__ __align__(16) float g_S   [Rr*Dc];
__device__ __align__(16) float g_H   [(size_t)RT*Dc];
__device__ __align__(16) float g_Qp  [Rr*Mc];

static __device__ __forceinline__ ull pk2(float lo, float hi){
    ull r; asm("mov.b64 %0, {%1, %2};" : "=l"(r) : "f"(lo), "f"(hi)); return r;
}
static __device__ __forceinline__ void ffma2(ull &d, ull a, ull b){
    asm("fma.rn.f32x2 %0, %1, %2, %0;" : "+l"(d) : "l"(a), "l"(b));
}
static __device__ __forceinline__ void upk2(ull v, float &lo, float &hi){
    asm("mov.b64 {%0, %1}, %2;" : "=f"(lo), "=f"(hi) : "l"(v));
}
static __device__ __forceinline__ float gelu_exact(float x){
    return 0.5f * x * (1.0f + erff(x * 0.70710678118654752f));
}

// ---------- LayerNorm (fused text+F in one launch) ----------
__global__ void ln_kernel(const float* __restrict__ in, float* __restrict__ out,
                          const float* __restrict__ gg, const float* __restrict__ bb){
    int row = blockIdx.x, t = threadIdx.x;
    float4 x = reinterpret_cast<const float4*>(in + (size_t)row*Dc)[t];
    float s = x.x+x.y+x.z+x.w;
    float q = x.x*x.x+x.y*x.y+x.z*x.z+x.w*x.w;
    #pragma unroll
    for (int o=16;o;o>>=1){ s += __shfl_xor_sync(0xffffffffu,s,o); q += __shfl_xor_sync(0xffffffffu,q,o); }
    __shared__ float ws[4], wq[4];
    if ((t&31)==0){ ws[t>>5]=s; wq[t>>5]=q; }
    __syncthreads();
    s = ws[0]+ws[1]+ws[2]+ws[3]; q = wq[0]+wq[1]+wq[2]+wq[3];
    float mu = s*(1.f/512.f);
    float rstd = rsqrtf(q*(1.f/512.f) - mu*mu + 1e-5f);
    float4 g4 = reinterpret_cast<const float4*>(gg)[t];
    float4 b4 = reinterpret_cast<const float4*>(bb)[t];
    float4 y;
    y.x=(x.x-mu)*rstd*g4.x+b4.x; y.y=(x.y-mu)*rstd*g4.y+b4.y;
    y.z=(x.z-mu)*rstd*g4.z+b4.z; y.w=(x.w-mu)*rstd*g4.w+b4.w;
    reinterpret_cast<float4*>(out + (size_t)row*Dc)[t] = y;
}

__global__ void ln1_fused(const float* __restrict__ text, const float* __restrict__ F,
                          const float* __restrict__ gg, const float* __restrict__ bb){
    int row = blockIdx.x, t = threadIdx.x;
    const float* in; float* out;
    if (row < Kc){ in = text + (size_t)row*Dc; out = g_qin + (size_t)row*Dc; }
    else { in = F + (size_t)(row-Kc)*Dc; out = g_kin + (size_t)(row-Kc)*Dc; }
    float4 x = reinterpret_cast<const float4*>(in)[t];
    float s = x.x+x.y+x.z+x.w;
    float q = x.x*x.x+x.y*x.y+x.z*x.z+x.w*x.w;
    #pragma unroll
    for (int o=16;o;o>>=1){ s += __shfl_xor_sync(0xffffffffu,s,o); q += __shfl_xor_sync(0xffffffffu,q,o); }
    __shared__ float ws[4], wq[4];
    if ((t&31)==0){ ws[t>>5]=s; wq[t>>5]=q; }
    __syncthreads();
    s = ws[0]+ws[1]+ws[2]+ws[3]; q = wq[0]+wq[1]+wq[2]+wq[3];
    float mu = s*(1.f/512.f);
    float rstd = rsqrtf(q*(1.f/512.f) - mu*mu + 1e-5f);
    float4 g4 = reinterpret_cast<const float4*>(gg)[t];
    float4 b4 = reinterpret_cast<const float4*>(bb)[t];
    float4 y;
    y.x=(x.x-mu)*rstd*g4.x+b4.x; y.y=(x.y-mu)*rstd*g4.y+b4.y;
    y.z=(x.z-mu)*rstd*g4.z+b4.z; y.w=(x.w-mu)*rstd*g4.w+b4.w;
    reinterpret_cast<float4*>(out)[t] = y;
}

// ---------- small SGEMM ----------
static __device__ __forceinline__
void sgemm_body(const float* __restrict__ A, const float* __restrict__ W,
                const float* __restrict__ bias, float* __restrict__ C, int Mrows){
    __shared__ float As[32][132];
    __shared__ float Bs[32][132];
    int t = threadIdx.x;
    int tx = t & 15, ty = t >> 4;
    int n0 = blockIdx.x * 128;
    int m0 = blockIdx.y * 128;
    ull acc[8][4];
    #pragma unroll
    for (int i=0;i<8;i++)
        #pragma unroll
        for (int j=0;j<4;j++) acc[i][j]=0ull;
    int la_r = t >> 3, la_c = (t & 7) * 4;
    for (int k0=0;k0<512;k0+=32){
        #pragma unroll
        for (int p=0;p<4;p++){
            int row = la_r + p*32;
            int gr = m0 + row;
            float4 va = make_float4(0.f,0.f,0.f,0.f);
            if (gr < Mrows) va = *reinterpret_cast<const float4*>(&A[(size_t)gr*512 + k0 + la_c]);
            As[la_c+0][row]=va.x; As[la_c+1][row]=va.y; As[la_c+2][row]=va.z; As[la_c+3][row]=va.w;
            float4 vb = *reinterpret_cast<const float4*>(&W[(size_t)(n0+row)*512 + k0 + la_c]);
            Bs[la_c+0][row]=vb.x; Bs[la_c+1][row]=vb.y; Bs[la_c+2][row]=vb.z; Bs[la_c+3][row]=vb.w;
        }
        __syncthreads();
        #pragma unroll
        for (int kk=0;kk<32;kk++){
            float4 a0 = *reinterpret_cast<const float4*>(&As[kk][ty*8]);
            float4 a1 = *reinterpret_cast<const float4*>(&As[kk][ty*8+4]);
            float4 b0 = *reinterpret_cast<const float4*>(&Bs[kk][tx*8]);
            float4 b1 = *reinterpret_cast<const float4*>(&Bs[kk][tx*8+4]);
            ull bp0=pk2(b0.x,b0.y), bp1=pk2(b0.z,b0.w), bp2=pk2(b1.x,b1.y), bp3=pk2(b1.z,b1.w);
            float av[8]={a0.x,a0.y,a0.z,a0.w,a1.x,a1.y,a1.z,a1.w};
            #pragma unroll
            for (int i=0;i<8;i++){
                ull ad = pk2(av[i], av[i]);
                ffma2(acc[i][0], ad, bp0); ffma2(acc[i][1], ad, bp1);
                ffma2(acc[i][2], ad, bp2); ffma2(acc[i][3], ad, bp3);
            }
        }
        __syncthreads();
    }
    #pragma unroll
    for (int i=0;i<8;i++){
        int row = m0 + ty*8 + i;
        if (row >= Mrows) continue;
        float* cp = &C[(size_t)row*512 + n0 + tx*8];
        const float* bp = &bias[n0 + tx*8];
        #pragma unroll
        for (int j=0;j<4;j++){
            float lo,hi; upk2(acc[i][j], lo, hi);
            cp[2*j] = lo + bp[2*j]; cp[2*j+1] = hi + bp[2*j+1];
        }
    }
}

__global__ __launch_bounds__(256)
void sgemm_nt(const float* __restrict__ A, const float* __restrict__ W,
              const float* __restrict__ bias, float* __restrict__ C, int Mrows){
    sgemm_body(A, W, bias, C, Mrows);
}

__global__ __launch_bounds__(256)
void sgemm_qkv(const float* __restrict__ F, const float* __restrict__ ipw,
               const float* __restrict__ ipb){
    int z = blockIdx.z;
    if (z == 0){ sgemm_body(g_kin, ipw + 512*512, ipb + 512, g_k, Rr); }
    else if (z == 1){ sgemm_body(F, ipw + 2*512*512, ipb + 1024, g_v, Rr); }
    else { if (blockIdx.y) return; sgemm_body(g_qin, ipw, ipb, g_q, Kc); }
}

// ---------- big GEMM: R9 config (single buffer, dup-pair A, 8x8, 256 thr) ----------
#define GB_SMEM ((32*256 + 32*132)*4)

__global__ __launch_bounds__(256, 2)
void gemm_big(const float* __restrict__ F, const float* __restrict__ w1,
              const float* __restrict__ b1){
    extern __shared__ float dsm[];
    float* As2 = dsm;            // 8192 floats
    float* Bsf = dsm + 32*256;   // 32*132 floats
    int t = threadIdx.x;
    int tx = t & 15, ty = t >> 4;
    int n0 = blockIdx.x * 128;
    int m0 = blockIdx.y * 128;
    int la_r = t >> 3, la_c = (t & 7) * 4;
    int cpr = t & 7;

    const float *fp[4], *ap[4], *sp[4];
    float wv[4];
    bool ok[4];
    #pragma unroll
    for (int p=0;p<4;p++){
        int gr = m0 + la_r + p*32;
        ok[p] = gr < RT;
        int grc = ok[p] ? gr : 0;
        int rn = grc / 77;
        int k  = grc - rn*77;
        int b  = rn / 196;
        wv[p] = g_w[(size_t)rn*77 + k];
        fp[p] = F   + (size_t)rn*512 + la_c;
        ap[p] = g_A + ((size_t)(b*77)+k)*512 + la_c;
        sp[p] = g_S + (size_t)rn*512 + la_c;
    }
    const float* wp = w1 + (size_t)(n0 + la_r)*512 + la_c;

    ull acc[8][4];
    #pragma unroll
    for (int i=0;i<8;i++)
        #pragma unroll
        for (int j=0;j<4;j++) acc[i][j]=0ull;

    for (int k0=0;k0<512;k0+=32){
        #pragma unroll
        for (int p=0;p<4;p++){
            int row = la_r + p*32;
            float4 F4 = *reinterpret_cast<const float4*>(fp[p] + k0);
            float4 A4 = *reinterpret_cast<const float4*>(ap[p] + k0);
            float4 S4 = *reinterpret_cast<const float4*>(sp[p] + k0);
            float4 x4;
            if (ok[p]){
                float wq = wv[p];
                x4.x = F4.x*(wq*A4.x - S4.x); x4.y = F4.y*(wq*A4.y - S4.y);
                x4.z = F4.z*(wq*A4.z - S4.z); x4.w = F4.w*(wq*A4.w - S4.w);
            } else x4 = make_float4(0.f,0.f,0.f,0.f);
            int chunk = row >> 1;
            int half = (row & 1) * 2;
            int boff = 4*(chunk ^ cpr) + half;
            float vtab[4] = {x4.x, x4.y, x4.z, x4.w};
            #pragma unroll
            for (int j=0;j<4;j++){
                *reinterpret_cast<float2*>(&As2[(la_c+j)*256 + boff]) = make_float2(vtab[j], vtab[j]);
            }
            float4 vb = *reinterpret_cast<const float4*>(wp + k0 + (size_t)p*32*512);
            Bsf[(la_c+0)*132 + row]=vb.x; Bsf[(la_c+1)*132 + row]=vb.y;
            Bsf[(la_c+2)*132 + row]=vb.z; Bsf[(la_c+3)*132 + row]=vb.w;
        }
        __syncthreads();
        #pragma unroll
        for (int kk=0;kk<32;kk++){
            int c2 = (kk>>2)&7;
            const float4* abase = reinterpret_cast<const float4*>(&As2[kk*256]);
            float4 Aq0 = abase[(4*ty+0) ^ c2];
            float4 Aq1 = abase[(4*ty+1) ^ c2];
            float4 Aq2 = abase[(4*ty+2) ^ c2];
            float4 Aq3 = abase[(4*ty+3) ^ c2];
            float4 b0 = *reinterpret_cast<const float4*>(&Bsf[kk*132 + tx*8]);
            float4 b1v = *reinterpret_cast<const float4*>(&Bsf[kk*132 + tx*8 + 4]);
            ull bp0=pk2(b0.x,b0.y), bp1=pk2(b0.z,b0.w), bp2=pk2(b1v.x,b1v.y), bp3=pk2(b1v.z,b1v.w);
            ull ad[8];
            ad[0]=pk2(Aq0.x,Aq0.y); ad[1]=pk2(Aq0.z,Aq0.w);
            ad[2]=pk2(Aq1.x,Aq1.y); ad[3]=pk2(Aq1.z,Aq1.w);
            ad[4]=pk2(Aq2.x,Aq2.y); ad[5]=pk2(Aq2.z,Aq2.w);
            ad[6]=pk2(Aq3.x,Aq3.y); ad[7]=pk2(Aq3.z,Aq3.w);
            #pragma unroll
            for (int i=0;i<8;i++){
                ffma2(acc[i][0], ad[i], bp0); ffma2(acc[i][1], ad[i], bp1);
                ffma2(acc[i][2], ad[i], bp2); ffma2(acc[i][3], ad[i], bp3);
            }
        }
        __syncthreads();
    }
    #pragma unroll
    for (int i=0;i<8;i++){
        int row = m0 + ty*8 + i;
        if (row >= RT) continue;
        float* cp = &g_H[(size_t)row*512 + n0 + tx*8];
        const float* bp = &b1[n0 + tx*8];
        #pragma unroll
        for (int j=0;j<4;j++){
            float lo,hi; upk2(acc[i][j], lo, hi);
            cp[2*j] = lo + bp[2*j]; cp[2*j+1] = hi + bp[2*j+1];
        }
    }
}

// ---------- attention (4-way ctx) ----------
__global__ void attn_kernel(){
    int kq = blockIdx.x, h = blockIdx.y, b = blockIdx.z;
    int t = threadIdx.x;
    __shared__ float sq[64];
    __shared__ float sc[196];
    __shared__ float red[8];
    __shared__ float ctxred[4][64];
    if (t < 64) sq[t] = g_q[kq*512 + h*64 + t];
    __syncthreads();
    float val = -1e30f;
    if (t < 196){
        const float* kr = &g_k[((size_t)(b*196 + t))*512 + h*64];
        float s = 0.f;
        #pragma unroll
        for (int d=0; d<64; d+=4){
            float4 k4 = *reinterpret_cast<const float4*>(&kr[d]);
            s += sq[d]*k4.x + sq[d+1]*k4.y + sq[d+2]*k4.z + sq[d+3]*k4.w;
        }
        val = s * 0.125f;
    }
    float mv = val;
    #pragma unroll
    for (int o=16;o;o>>=1) mv = fmaxf(mv, __shfl_xor_sync(0xffffffffu, mv, o));
    if ((t&31)==0) red[t>>5] = mv;
    __syncthreads();
    float rm = red[0];
    #pragma unroll
    for (int i=1;i<8;i++) rm = fmaxf(rm, red[i]);
    float e = (t<196) ? expf(val - rm) : 0.f;
    float se = e;
    #pragma unroll
    for (int o=16;o;o>>=1) se += __shfl_xor_sync(0xffffffffu, se, o);
    __syncthreads();
    if ((t&31)==0) red[t>>5] = se;
    __syncthreads();
    float tot = red[0]+red[1]+red[2]+red[3]+red[4]+red[5]+red[6]+red[7];
    float a = e / tot;
    if (t < 196){
        sc[t] = a;
        g_attn[(((size_t)(b*Hc+h))*Kc + kq)*Nc + t] = a;
    }
    __syncthreads();
    {
        int g = t >> 6, d = t & 63;
        const float* vb = &g_v[((size_t)(b*196))*512 + h*64 + d];
        float acc = 0.f;
        for (int n = g; n < 196; n += 4) acc += sc[n]*vb[(size_t)n*512];
        ctxred[g][d] = acc;
    }
    __syncthreads();
    if (t < 64){
        float r = ctxred[0][t]+ctxred[1][t]+ctxred[2][t]+ctxred[3][t];
        g_ctx[((size_t)(b*Kc)+kq)*512 + h*64 + t] = r;
    }
}

__global__ void aw_kernel(float* __restrict__ out_aw){
    int k = blockIdx.x, b = blockIdx.y;
    int n = threadIdx.x;
    if (n < 196){
        float s = 0.f;
        #pragma unroll
        for (int h=0;h<8;h++) s += g_attn[(((size_t)(b*Hc+h))*Kc + k)*Nc + n];
        s *= 0.125f;
        out_aw[((size_t)(b*Kc)+k)*Nc + n] = s;
        g_w[((size_t)(b*196+n))*Kc + k] = s;
    }
}

__global__ void sbar_kernel(){
    int r = blockIdx.x;
    int b = r / 196;
    int t = threadIdx.x;
    __shared__ float ws[Kc];
    for (int i=t;i<Kc;i+=128) ws[i] = g_w[(size_t)r*Kc + i];
    __syncthreads();
    float4 acc = make_float4(0.f,0.f,0.f,0.f);
    const float4* Ab = reinterpret_cast<const float4*>(&g_A[(size_t)b*Kc*512]);
    for (int k=0;k<Kc;k++){
        float wv = ws[k];
        float4 a4 = Ab[(size_t)k*128 + t];
        acc.x += wv*a4.x; acc.y += wv*a4.y; acc.z += wv*a4.z; acc.w += wv*a4.w;
    }
    float inv = 1.0f/77.0f;
    acc.x*=inv; acc.y*=inv; acc.z*=inv; acc.w*=inv;
    reinterpret_cast<float4*>(&g_S[(size_t)r*512])[t] = acc;
}

// ---------- H -> Qp (f32x2 W2 dot) ----------
__global__ __launch_bounds__(640)
void h2qp(const float* __restrict__ w2, const float* __restrict__ b2,
          const float* __restrict__ lng, const float* __restrict__ lnb){
    int rn = blockIdx.x;
    int t = threadIdx.x;
    int wid = t >> 5, lane = t & 31;
    __shared__ float sW[Mc*512];
    __shared__ float sg[512], sb[512];
    __shared__ float ws[80];
    __shared__ float sacc[Mc*Mc];
    for (int i=t;i<2560;i+=640) reinterpret_cast<float4*>(sW)[i] = reinterpret_cast<const float4*>(w2)[i];
    for (int i=t;i<128;i+=640){
        reinterpret_cast<float4*>(sg)[i] = reinterpret_cast<const float4*>(lng)[i];
        reinterpret_cast<float4*>(sb)[i] = reinterpret_cast<const float4*>(lnb)[i];
    }
    if (t < 77) ws[t] = g_w[(size_t)rn*77 + t];
    __syncthreads();
    float wsum = 0.f;
    #pragma unroll 7
    for (int k=0;k<77;k++) wsum += ws[k];

    float accL[Mc];
    #pragma unroll
    for (int m=0;m<Mc;m++) accL[m] = 0.f;

    for (int k = wid; k < 77; k += 20){
        const float* hp = &g_H[((size_t)rn*77 + k)*512];
        float4 h4[4];
        #pragma unroll
        for (int i=0;i<4;i++) h4[i] = *reinterpret_cast<const float4*>(&hp[128*i + lane*4]);
        float s = 0.f, q = 0.f;
        #pragma unroll
        for (int i=0;i<4;i++){
            s += h4[i].x + h4[i].y + h4[i].z + h4[i].w;
            q += h4[i].x*h4[i].x + h4[i].y*h4[i].y + h4[i].z*h4[i].z + h4[i].w*h4[i].w;
        }
        #pragma unroll
        for (int o=16;o;o>>=1){
            s += __shfl_xor_sync(0xffffffffu, s, o);
            q += __shfl_xor_sync(0xffffffffu, q, o);
        }
        float mu = s*(1.f/512.f);
        float rstd = rsqrtf(q*(1.f/512.f) - mu*mu + 1e-5f);
        ull yp[8];
        #pragma unroll
        for (int i=0;i<4;i++){
            int col = 128*i + lane*4;
            float y0 = gelu_exact((h4[i].x - mu)*rstd*sg[col+0] + sb[col+0]);
            float y1 = gelu_exact((h4[i].y - mu)*rstd*sg[col+1] + sb[col+1]);
            float y2 = gelu_exact((h4[i].z - mu)*rstd*sg[col+2] + sb[col+2]);
            float y3 = gelu_exact((h4[i].w - mu)*rstd*sg[col+3] + sb[col+3]);
            yp[2*i]   = pk2(y0, y1);
            yp[2*i+1] = pk2(y2, y3);
        }
        float wk = ws[k];
        #pragma unroll
        for (int m=0;m<Mc;m++){
            const float4* wm = reinterpret_cast<const float4*>(&sW[m*512]);
            ull a2 = 0ull;
            #pragma unroll
            for (int i=0;i<4;i++){
                float4 c4 = wm[32*i + lane];
                ffma2(a2, yp[2*i],   pk2(c4.x, c4.y));
                ffma2(a2, yp[2*i+1], pk2(c4.z, c4.w));
            }
            float lo, hi; upk2(a2, lo, hi);
            accL[m] += wk*(lo + hi);
        }
    }
    #pragma unroll
    for (int m=0;m<Mc;m++){
        float a = accL[m];
        #pragma unroll
        for (int o=16;o;o>>=1) a += __shfl_xor_sync(0xffffffffu, a, o);
        if (lane == 0) sacc[wid*Mc + m] = a;
    }
    __syncthreads();
    if (t < Mc){
        float a = 0.f;
        #pragma unroll
        for (int w2i=0;w2i<Mc;w2i++) a += sacc[w2i*Mc + t];
        g_Qp[(size_t)rn*Mc + t] = a + b2[t]*wsum;
    }
}

// ---------- top-51 + normalize + output ----------
__global__ void topk_kernel(const float* __restrict__ F, const float* __restrict__ T,
                            float* __restrict__ out){
    int r = blockIdx.x;
    int m = blockIdx.y;
    int t = threadIdx.x;
    __shared__ uint hist[256];
    __shared__ uint sh_pref, sh_rem;
    __shared__ uint wsum[4];
    __shared__ uint wtot[4];
    __shared__ float sred[4];

    float Qp = g_Qp[(size_t)r*Mc + m];
    float4 F4 = reinterpret_cast<const float4*>(&F[(size_t)r*512])[t];
    float4 T4 = reinterpret_cast<const float4*>(&T[(size_t)m*512])[t];
    float q0=F4.x*T4.x, q1=F4.y*T4.y, q2=F4.z*T4.z, q3=F4.w*T4.w;
    uint k0=__float_as_uint(fabsf(q0)), k1=__float_as_uint(fabsf(q1));
    uint k2=__float_as_uint(fabsf(q2)), k3=__float_as_uint(fabsf(q3));

    uint lane = t & 31, wid = t >> 5;
    uint pref = 0, hmask = 0, rem = KKEEP;
    for (int bp=3; bp>=0; bp--){
        hist[t] = 0; hist[t+128] = 0;
        __syncthreads();
        uint bm = hmask, p = pref;
        if ((k0 & bm) == p) atomicAdd(&hist[(k0 >> (bp*8)) & 255u], 1u);
        if ((k1 & bm) == p) atomicAdd(&hist[(k1 >> (bp*8)) & 255u], 1u);
        if ((k2 & bm) == p) atomicAdd(&hist[(k2 >> (bp*8)) & 255u], 1u);
        if ((k3 & bm) == p) atomicAdd(&hist[(k3 >> (bp*8)) & 255u], 1u);
        __syncthreads();
        uint h_lo = hist[2*t], h_hi = hist[2*t+1];
        uint pairv = h_lo + h_hi;
        uint v = pairv;
        #pragma unroll
        for (int o=1;o<32;o<<=1){
            uint u = __shfl_down_sync(0xffffffffu, v, o);
            if (lane < 32-o) v += u;
        }
        if (lane == 0) wtot[wid] = v;
        __syncthreads();
        uint tail = 0;
        for (uint wq = wid+1; wq < 4; wq++) tail += wtot[wq];
        uint Spair = v + tail;
        uint S0 = Spair;
        uint S1 = Spair - h_lo;
        uint S2 = Spair - pairv;
        if (S1 >= rem && S2 < rem){
            sh_pref = pref | ((uint)(2*t+1) << (bp*8));
            sh_rem = rem - S2;
        }
        if (S0 >= rem && S1 < rem){
            sh_pref = pref | ((uint)(2*t) << (bp*8));
            sh_rem = rem - S1;
        }
        __syncthreads();
        pref = sh_pref; rem = sh_rem;
        hmask |= (255u << (bp*8));
        __syncthreads();
    }
    uint thr = pref, req = rem;

    uint e0 = (k0==thr), e1 = (k1==thr), e2 = (k2==thr), e3 = (k3==thr);
    uint tc = e0+e1+e2+e3;
    uint inc = tc;
    #pragma unroll
    for (int o=1;o<32;o<<=1){
        uint v = __shfl_up_sync(0xffffffffu, inc, o);
        if (lane >= o) inc += v;
    }
    if (lane == 31) wsum[wid] = inc;
    __syncthreads();
    uint woff = 0;
    for (uint i=0;i<wid;i++) woff += wsum[i];
    uint p0 = woff + inc - tc;
    uint p1 = p0 + e0, p2 = p1 + e1, p3 = p2 + e2;
    bool s0 = (k0 > thr) || (e0 && p0 < req);
    bool s1 = (k1 > thr) || (e1 && p1 < req);
    bool s2 = (k2 > thr) || (e2 && p2 < req);
    bool s3 = (k3 > thr) || (e3 && p3 < req);

    float v0 = Qp*q0, v1 = Qp*q1, v2 = Qp*q2, v3 = Qp*q3;
    float ss = (s0?v0*v0:0.f) + (s1?v1*v1:0.f) + (s2?v2*v2:0.f) + (s3?v3*v3:0.f);
    #pragma unroll
    for (int o=16;o;o>>=1) ss += __shfl_xor_sync(0xffffffffu, ss, o);
    if (lane == 0) sred[wid] = ss;
    __syncthreads();
    float tot = sred[0]+sred[1]+sred[2]+sred[3];
    float nrm = fmaxf(sqrtf(tot), 1e-6f);
    float invn = 1.0f / nrm;

    size_t base = ((size_t)r*512 + (size_t)t*4)*Mc + m;
    out[base       ] = s0 ? v0*invn : 0.f;
    out[base +   Mc] = s1 ? v1*invn : 0.f;
    out[base + 2*Mc] = s2 ? v2*invn : 0.f;
    out[base + 3*Mc] = s3 ? v3*invn : 0.f;
}

// ---------- launch ----------
extern "C" void kernel_launch(void* const* d_in, const int* in_sizes, int n_in,
                              void* d_out, int out_size){
    const float* F    = (const float*)d_in[0];
    const float* text = (const float*)d_in[1];
    const float* ipw  = (const float*)d_in[2];
    const float* ipb  = (const float*)d_in[3];
    const float* outw = (const float*)d_in[4];
    const float* outb = (const float*)d_in[5];
    const float* ln1g = (const float*)d_in[6];
    const float* ln1b = (const float*)d_in[7];
    const float* ln2g = (const float*)d_in[8];
    const float* ln2b = (const float*)d_in[9];
    const float* w1   = (const float*)d_in[10];
    const float* b1   = (const float*)d_in[11];
    const float* mlng = (const float*)d_in[12];
    const float* mlnb = (const float*)d_in[13];
    const float* w2   = (const float*)d_in[14];
    const float* b2   = (const float*)d_in[15];
    const float* tmpl = (const float*)d_in[16];
    float* out = (float*)d_out;

    float *p_ctx, *p_A;
    cudaGetSymbolAddress((void**)&p_ctx, g_ctx);
    cudaGetSymbolAddress((void**)&p_A,   g_A);

    cudaFuncSetAttribute(gemm_big, cudaFuncAttributeMaxDynamicSharedMemorySize, GB_SMEM);

    ln1_fused<<<Kc + Rr, 128>>>(text, F, ln1g, ln1b);

    sgemm_qkv<<<dim3(4,13,3), 256>>>(F, ipw, ipb);

    attn_kernel<<<dim3(Kc, Hc, Bc), 256>>>();
    aw_kernel<<<dim3(Kc, Bc), 224>>>(out + QS_ELEMS);

    sgemm_nt<<<dim3(4,5), 256>>>(p_ctx, outw, outb, p_A, Bc*Kc);
    ln_kernel<<<Bc*Kc, 128>>>(p_A, p_A, ln2g, ln2b);

    sbar_kernel<<<Rr, 128>>>();

    gemm_big<<<dim3(4, (RT + 127)/128), 256, GB_SMEM>>>(F, w1, b1);

    h2qp<<<Rr, 640>>>(w2, b2, mlng, mlnb);

    topk_kernel<<<dim3(Rr, Mc), 128>>>(F, tmpl, out);
}

// round 13
// speedup vs baseline: 1.1752x; 1.0449x over previous
#include <cuda_runtime.h>
#include <math.h>

#define Bc 8
#define Nc 196
#define Dc 512
#define Mc 20
#define Kc 77
#define Hc 8
#define Rr (Bc*Nc)
#define RT (Rr*Kc)
#define QS_ELEMS (Bc*Nc*Dc*Mc)
#define KKEEP 51u

typedef unsigned int uint;
typedef unsigned long long ull;

__device__ __align__(16) float g_qin [Kc*Dc];
__device__ __align__(16) float g_kin [Rr*Dc];
__device__ __align__(16) float g_q   [Kc*Dc];
__device__ __align__(16) float g_k   [Rr*Dc];
__device__ __align__(16) float g_v   [Rr*Dc];
__device__ __align__(16) float g_attn[Bc*Hc*Kc*Nc];
__device__ __align__(16) float g_ctx [Bc*Kc*Dc];
__device__ __align__(16) float g_A   [Bc*Kc*Dc];
__device__ __align__(16) float g_w   [Rr*Kc];
__device__ __align__(16) float g_S   [Rr*Dc];
__device__ __align__(16) float g_H   [(size_t)RT*Dc];
__device__ __align__(16) float g_Qp  [Rr*Mc];

static __device__ __forceinline__ ull pk2(float lo, float hi){
    ull r; asm("mov.b64 %0, {%1, %2};" : "=l"(r) : "f"(lo), "f"(hi)); return r;
}
static __device__ __forceinline__ void ffma2(ull &d, ull a, ull b){
    asm("fma.rn.f32x2 %0, %1, %2, %0;" : "+l"(d) : "l"(a), "l"(b));
}
static __device__ __forceinline__ void upk2(ull v, float &lo, float &hi){
    asm("mov.b64 {%0, %1}, %2;" : "=f"(lo), "=f"(hi) : "l"(v));
}
static __device__ __forceinline__ float gelu_exact(float x){
    return 0.5f * x * (1.0f + erff(x * 0.70710678118654752f));
}
static __device__ __forceinline__ uint tf32u(float x){
    uint u; asm("cvt.rna.tf32.f32 %0, %1;" : "=r"(u) : "f"(x)); return u;
}
static __device__ __forceinline__ void mma8(float4 &c, uint a0,uint a1,uint a2,uint a3,
                                            uint b0, uint b1){
    asm("mma.sync.aligned.m16n8k8.row.col.f32.tf32.tf32.f32 "
        "{%0,%1,%2,%3},{%4,%5,%6,%7},{%8,%9},{%0,%1,%2,%3};"
        : "+f"(c.x),"+f"(c.y),"+f"(c.z),"+f"(c.w)
        : "r"(a0),"r"(a1),"r"(a2),"r"(a3),"r"(b0),"r"(b1));
}

// ---------- LayerNorm ----------
__global__ void ln_kernel(const float* __restrict__ in, float* __restrict__ out,
                          const float* __restrict__ gg, const float* __restrict__ bb){
    int row = blockIdx.x, t = threadIdx.x;
    float4 x = reinterpret_cast<const float4*>(in + (size_t)row*Dc)[t];
    float s = x.x+x.y+x.z+x.w;
    float q = x.x*x.x+x.y*x.y+x.z*x.z+x.w*x.w;
    #pragma unroll
    for (int o=16;o;o>>=1){ s += __shfl_xor_sync(0xffffffffu,s,o); q += __shfl_xor_sync(0xffffffffu,q,o); }
    __shared__ float ws[4], wq[4];
    if ((t&31)==0){ ws[t>>5]=s; wq[t>>5]=q; }
    __syncthreads();
    s = ws[0]+ws[1]+ws[2]+ws[3]; q = wq[0]+wq[1]+wq[2]+wq[3];
    float mu = s*(1.f/512.f);
    float rstd = rsqrtf(q*(1.f/512.f) - mu*mu + 1e-5f);
    float4 g4 = reinterpret_cast<const float4*>(gg)[t];
    float4 b4 = reinterpret_cast<const float4*>(bb)[t];
    float4 y;
    y.x=(x.x-mu)*rstd*g4.x+b4.x; y.y=(x.y-mu)*rstd*g4.y+b4.y;
    y.z=(x.z-mu)*rstd*g4.z+b4.z; y.w=(x.w-mu)*rstd*g4.w+b4.w;
    reinterpret_cast<float4*>(out + (size_t)row*Dc)[t] = y;
}

__global__ void ln1_fused(const float* __restrict__ text, const float* __restrict__ F,
                          const float* __restrict__ gg, const float* __restrict__ bb){
    int row = blockIdx.x, t = threadIdx.x;
    const float* in; float* out;
    if (row < Kc){ in = text + (size_t)row*Dc; out = g_qin + (size_t)row*Dc; }
    else { in = F + (size_t)(row-Kc)*Dc; out = g_kin + (size_t)(row-Kc)*Dc; }
    float4 x = reinterpret_cast<const float4*>(in)[t];
    float s = x.x+x.y+x.z+x.w;
    float q = x.x*x.x+x.y*x.y+x.z*x.z+x.w*x.w;
    #pragma unroll
    for (int o=16;o;o>>=1){ s += __shfl_xor_sync(0xffffffffu,s,o); q += __shfl_xor_sync(0xffffffffu,q,o); }
    __shared__ float ws[4], wq[4];
    if ((t&31)==0){ ws[t>>5]=s; wq[t>>5]=q; }
    __syncthreads();
    s = ws[0]+ws[1]+ws[2]+ws[3]; q = wq[0]+wq[1]+wq[2]+wq[3];
    float mu = s*(1.f/512.f);
    float rstd = rsqrtf(q*(1.f/512.f) - mu*mu + 1e-5f);
    float4 g4 = reinterpret_cast<const float4*>(gg)[t];
    float4 b4 = reinterpret_cast<const float4*>(bb)[t];
    float4 y;
    y.x=(x.x-mu)*rstd*g4.x+b4.x; y.y=(x.y-mu)*rstd*g4.y+b4.y;
    y.z=(x.z-mu)*rstd*g4.z+b4.z; y.w=(x.w-mu)*rstd*g4.w+b4.w;
    reinterpret_cast<float4*>(out)[t] = y;
}

// ---------- small SGEMM ----------
static __device__ __forceinline__
void sgemm_body(const float* __restrict__ A, const float* __restrict__ W,
                const float* __restrict__ bias, float* __restrict__ C, int Mrows){
    __shared__ float As[32][132];
    __shared__ float Bs[32][132];
    int t = threadIdx.x;
    int tx = t & 15, ty = t >> 4;
    int n0 = blockIdx.x * 128;
    int m0 = blockIdx.y * 128;
    ull acc[8][4];
    #pragma unroll
    for (int i=0;i<8;i++)
        #pragma unroll
        for (int j=0;j<4;j++) acc[i][j]=0ull;
    int la_r = t >> 3, la_c = (t & 7) * 4;
    for (int k0=0;k0<512;k0+=32){
        #pragma unroll
        for (int p=0;p<4;p++){
            int row = la_r + p*32;
            int gr = m0 + row;
            float4 va = make_float4(0.f,0.f,0.f,0.f);
            if (gr < Mrows) va = *reinterpret_cast<const float4*>(&A[(size_t)gr*512 + k0 + la_c]);
            As[la_c+0][row]=va.x; As[la_c+1][row]=va.y; As[la_c+2][row]=va.z; As[la_c+3][row]=va.w;
            float4 vb = *reinterpret_cast<const float4*>(&W[(size_t)(n0+row)*512 + k0 + la_c]);
            Bs[la_c+0][row]=vb.x; Bs[la_c+1][row]=vb.y; Bs[la_c+2][row]=vb.z; Bs[la_c+3][row]=vb.w;
        }
        __syncthreads();
        #pragma unroll
        for (int kk=0;kk<32;kk++){
            float4 a0 = *reinterpret_cast<const float4*>(&As[kk][ty*8]);
            float4 a1 = *reinterpret_cast<const float4*>(&As[kk][ty*8+4]);
            float4 b0 = *reinterpret_cast<const float4*>(&Bs[kk][tx*8]);
            float4 b1 = *reinterpret_cast<const float4*>(&Bs[kk][tx*8+4]);
            ull bp0=pk2(b0.x,b0.y), bp1=pk2(b0.z,b0.w), bp2=pk2(b1.x,b1.y), bp3=pk2(b1.z,b1.w);
            float av[8]={a0.x,a0.y,a0.z,a0.w,a1.x,a1.y,a1.z,a1.w};
            #pragma unroll
            for (int i=0;i<8;i++){
                ull ad = pk2(av[i], av[i]);
                ffma2(acc[i][0], ad, bp0); ffma2(acc[i][1], ad, bp1);
                ffma2(acc[i][2], ad, bp2); ffma2(acc[i][3], ad, bp3);
            }
        }
        __syncthreads();
    }
    #pragma unroll
    for (int i=0;i<8;i++){
        int row = m0 + ty*8 + i;
        if (row >= Mrows) continue;
        float* cp = &C[(size_t)row*512 + n0 + tx*8];
        const float* bp = &bias[n0 + tx*8];
        #pragma unroll
        for (int j=0;j<4;j++){
            float lo,hi; upk2(acc[i][j], lo, hi);
            cp[2*j] = lo + bp[2*j]; cp[2*j+1] = hi + bp[2*j+1];
        }
    }
}

__global__ __launch_bounds__(256)
void sgemm_nt(const float* __restrict__ A, const float* __restrict__ W,
              const float* __restrict__ bias, float* __restrict__ C, int Mrows){
    sgemm_body(A, W, bias, C, Mrows);
}

__global__ __launch_bounds__(256)
void sgemm_qkv(const float* __restrict__ F, const float* __restrict__ ipw,
               const float* __restrict__ ipb){
    int z = blockIdx.z;
    if (z == 0){ sgemm_body(g_kin, ipw + 512*512, ipb + 512, g_k, Rr); }
    else if (z == 1){ sgemm_body(F, ipw + 2*512*512, ipb + 1024, g_v, Rr); }
    else { if (blockIdx.y) return; sgemm_body(g_qin, ipw, ipb, g_q, Kc); }
}

// ---------- big GEMM: 3xTF32 mma.sync, X on the fly ----------
// planes: Ah, Al, Bh, Bl each 128 rows x 34 uints (k-interleaved pos = (k&3)*8 + (k>>2))
#define GP 34
#define GMM_SMEM (4*128*GP*4)

__global__ __launch_bounds__(256, 2)
void gemm_big(const float* __restrict__ F, const float* __restrict__ w1,
              const float* __restrict__ b1){
    extern __shared__ uint usm[];
    uint* Ah = usm;
    uint* Al = Ah + 128*GP;
    uint* Bh = Al + 128*GP;
    uint* Bl = Bh + 128*GP;
    int t = threadIdx.x;
    int lane = t & 31, wid = t >> 5;
    int warpM = wid & 3, warpN = wid >> 2;   // 4 x 2 warps
    int g = lane >> 2, tg = lane & 3;
    int n0 = blockIdx.x * 128;
    int m0 = blockIdx.y * 128;
    int la_r = t >> 3, la_c = (t & 7) * 4;
    int c8 = t & 7;                          // pos offset for this thread's kcols

    const float *fp[4], *ap[4], *sp[4];
    float wv[4];
    bool ok[4];
    #pragma unroll
    for (int p=0;p<4;p++){
        int gr = m0 + la_r + p*32;
        ok[p] = gr < RT;
        int grc = ok[p] ? gr : 0;
        int rn = grc / 77;
        int k  = grc - rn*77;
        int b  = rn / 196;
        wv[p] = g_w[(size_t)rn*77 + k];
        fp[p] = F   + (size_t)rn*512 + la_c;
        ap[p] = g_A + ((size_t)(b*77)+k)*512 + la_c;
        sp[p] = g_S + (size_t)rn*512 + la_c;
    }
    const float* wp = w1 + (size_t)(n0 + la_r)*512 + la_c;

    float4 acc[2][8];
    #pragma unroll
    for (int i=0;i<2;i++)
        #pragma unroll
        for (int j=0;j<8;j++) acc[i][j] = make_float4(0.f,0.f,0.f,0.f);

    for (int k0=0;k0<512;k0+=32){
        #pragma unroll
        for (int p=0;p<4;p++){
            int row = la_r + p*32;
            float4 F4 = *reinterpret_cast<const float4*>(fp[p] + k0);
            float4 A4 = *reinterpret_cast<const float4*>(ap[p] + k0);
            float4 S4 = *reinterpret_cast<const float4*>(sp[p] + k0);
            float xv[4];
            if (ok[p]){
                float wq = wv[p];
                xv[0] = F4.x*(wq*A4.x - S4.x); xv[1] = F4.y*(wq*A4.y - S4.y);
                xv[2] = F4.z*(wq*A4.z - S4.z); xv[3] = F4.w*(wq*A4.w - S4.w);
            } else { xv[0]=xv[1]=xv[2]=xv[3]=0.f; }
            float4 W4 = *reinterpret_cast<const float4*>(wp + k0 + (size_t)p*32*512);
            float bv[4] = {W4.x, W4.y, W4.z, W4.w};
            #pragma unroll
            for (int j=0;j<4;j++){
                uint hx = tf32u(xv[j]);
                uint lx = tf32u(xv[j] - __uint_as_float(hx));
                Ah[row*GP + j*8 + c8] = hx;
                Al[row*GP + j*8 + c8] = lx;
                uint hb = tf32u(bv[j]);
                uint lb = tf32u(bv[j] - __uint_as_float(hb));
                Bh[row*GP + j*8 + c8] = hb;
                Bl[row*GP + j*8 + c8] = lb;
            }
        }
        __syncthreads();
        #pragma unroll
        for (int pass=0; pass<3; pass++){
            const uint* pA = (pass==2) ? Al : Ah;
            const uint* pB = (pass==1) ? Bl : Bh;
            #pragma unroll
            for (int s=0;s<4;s++){
                uint2 bfr[8];
                #pragma unroll
                for (int j=0;j<8;j++)
                    bfr[j] = *reinterpret_cast<const uint2*>(&pB[(warpN*64 + j*8 + g)*GP + tg*8 + 2*s]);
                #pragma unroll
                for (int i=0;i<2;i++){
                    const uint* ra = &pA[(warpM*32 + i*16 + g)*GP + tg*8 + 2*s];
                    uint2 a02 = *reinterpret_cast<const uint2*>(ra);
                    uint2 a13 = *reinterpret_cast<const uint2*>(ra + 8*GP);
                    #pragma unroll
                    for (int j=0;j<8;j++)
                        mma8(acc[i][j], a02.x, a13.x, a02.y, a13.y, bfr[j].x, bfr[j].y);
                }
            }
        }
        __syncthreads();
    }

    #pragma unroll
    for (int i=0;i<2;i++){
        int r0 = m0 + warpM*32 + i*16 + g;
        int r1 = r0 + 8;
        #pragma unroll
        for (int j=0;j<8;j++){
            int col = n0 + warpN*64 + j*8 + 2*tg;
            float2 bb = *reinterpret_cast<const float2*>(&b1[col]);
            if (r0 < RT){
                float2 o0 = make_float2(acc[i][j].x + bb.x, acc[i][j].y + bb.y);
                *reinterpret_cast<float2*>(&g_H[(size_t)r0*512 + col]) = o0;
            }
            if (r1 < RT){
                float2 o1 = make_float2(acc[i][j].z + bb.x, acc[i][j].w + bb.y);
                *reinterpret_cast<float2*>(&g_H[(size_t)r1*512 + col]) = o1;
            }
        }
    }
}

// ---------- attention (4-way ctx) ----------
__global__ void attn_kernel(){
    int kq = blockIdx.x, h = blockIdx.y, b = blockIdx.z;
    int t = threadIdx.x;
    __shared__ float sq[64];
    __shared__ float sc[196];
    __shared__ float red[8];
    __shared__ float ctxred[4][64];
    if (t < 64) sq[t] = g_q[kq*512 + h*64 + t];
    __syncthreads();
    float val = -1e30f;
    if (t < 196){
        const float* kr = &g_k[((size_t)(b*196 + t))*512 + h*64];
        float s = 0.f;
        #pragma unroll
        for (int d=0; d<64; d+=4){
            float4 k4 = *reinterpret_cast<const float4*>(&kr[d]);
            s += sq[d]*k4.x + sq[d+1]*k4.y + sq[d+2]*k4.z + sq[d+3]*k4.w;
        }
        val = s * 0.125f;
    }
    float mv = val;
    #pragma unroll
    for (int o=16;o;o>>=1) mv = fmaxf(mv, __shfl_xor_sync(0xffffffffu, mv, o));
    if ((t&31)==0) red[t>>5] = mv;
    __syncthreads();
    float rm = red[0];
    #pragma unroll
    for (int i=1;i<8;i++) rm = fmaxf(rm, red[i]);
    float e = (t<196) ? expf(val - rm) : 0.f;
    float se = e;
    #pragma unroll
    for (int o=16;o;o>>=1) se += __shfl_xor_sync(0xffffffffu, se, o);
    __syncthreads();
    if ((t&31)==0) red[t>>5] = se;
    __syncthreads();
    float tot = red[0]+red[1]+red[2]+red[3]+red[4]+red[5]+red[6]+red[7];
    float a = e / tot;
    if (t < 196){
        sc[t] = a;
        g_attn[(((size_t)(b*Hc+h))*Kc + kq)*Nc + t] = a;
    }
    __syncthreads();
    {
        int g = t >> 6, d = t & 63;
        const float* vb = &g_v[((size_t)(b*196))*512 + h*64 + d];
        float acc = 0.f;
        for (int n = g; n < 196; n += 4) acc += sc[n]*vb[(size_t)n*512];
        ctxred[g][d] = acc;
    }
    __syncthreads();
    if (t < 64){
        float r = ctxred[0][t]+ctxred[1][t]+ctxred[2][t]+ctxred[3][t];
        g_ctx[((size_t)(b*Kc)+kq)*512 + h*64 + t] = r;
    }
}

__global__ void aw_kernel(float* __restrict__ out_aw){
    int k = blockIdx.x, b = blockIdx.y;
    int n = threadIdx.x;
    if (n < 196){
        float s = 0.f;
        #pragma unroll
        for (int h=0;h<8;h++) s += g_attn[(((size_t)(b*Hc+h))*Kc + k)*Nc + n];
        s *= 0.125f;
        out_aw[((size_t)(b*Kc)+k)*Nc + n] = s;
        g_w[((size_t)(b*196+n))*Kc + k] = s;
    }
}

__global__ void sbar_kernel(){
    int r = blockIdx.x;
    int b = r / 196;
    int t = threadIdx.x;
    __shared__ float ws[Kc];
    for (int i=t;i<Kc;i+=128) ws[i] = g_w[(size_t)r*Kc + i];
    __syncthreads();
    float4 acc = make_float4(0.f,0.f,0.f,0.f);
    const float4* Ab = reinterpret_cast<const float4*>(&g_A[(size_t)b*Kc*512]);
    for (int k=0;k<Kc;k++){
        float wv = ws[k];
        float4 a4 = Ab[(size_t)k*128 + t];
        acc.x += wv*a4.x; acc.y += wv*a4.y; acc.z += wv*a4.z; acc.w += wv*a4.w;
    }
    float inv = 1.0f/77.0f;
    acc.x*=inv; acc.y*=inv; acc.z*=inv; acc.w*=inv;
    reinterpret_cast<float4*>(&g_S[(size_t)r*512])[t] = acc;
}

// ---------- H -> Qp (f32x2 W2 dot) ----------
__global__ __launch_bounds__(640)
void h2qp(const float* __restrict__ w2, const float* __restrict__ b2,
          const float* __restrict__ lng, const float* __restrict__ lnb){
    int rn = blockIdx.x;
    int t = threadIdx.x;
    int wid = t >> 5, lane = t & 31;
    __shared__ float sW[Mc*512];
    __shared__ float sg[512], sb[512];
    __shared__ float ws[80];
    __shared__ float sacc[Mc*Mc];
    for (int i=t;i<2560;i+=640) reinterpret_cast<float4*>(sW)[i] = reinterpret_cast<const float4*>(w2)[i];
    for (int i=t;i<128;i+=640){
        reinterpret_cast<float4*>(sg)[i] = reinterpret_cast<const float4*>(lng)[i];
        reinterpret_cast<float4*>(sb)[i] = reinterpret_cast<const float4*>(lnb)[i];
    }
    if (t < 77) ws[t] = g_w[(size_t)rn*77 + t];
    __syncthreads();
    float wsum = 0.f;
    #pragma unroll 7
    for (int k=0;k<77;k++) wsum += ws[k];

    float accL[Mc];
    #pragma unroll
    for (int m=0;m<Mc;m++) accL[m] = 0.f;

    for (int k = wid; k < 77; k += 20){
        const float* hp = &g_H[((size_t)rn*77 + k)*512];
        float4 h4[4];
        #pragma unroll
        for (int i=0;i<4;i++) h4[i] = *reinterpret_cast<const float4*>(&hp[128*i + lane*4]);
        float s = 0.f, q = 0.f;
        #pragma unroll
        for (int i=0;i<4;i++){
            s += h4[i].x + h4[i].y + h4[i].z + h4[i].w;
            q += h4[i].x*h4[i].x + h4[i].y*h4[i].y + h4[i].z*h4[i].z + h4[i].w*h4[i].w;
        }
        #pragma unroll
        for (int o=16;o;o>>=1){
            s += __shfl_xor_sync(0xffffffffu, s, o);
            q += __shfl_xor_sync(0xffffffffu, q, o);
        }
        float mu = s*(1.f/512.f);
        float rstd = rsqrtf(q*(1.f/512.f) - mu*mu + 1e-5f);
        ull yp[8];
        #pragma unroll
        for (int i=0;i<4;i++){
            int col = 128*i + lane*4;
            float y0 = gelu_exact((h4[i].x - mu)*rstd*sg[col+0] + sb[col+0]);
            float y1 = gelu_exact((h4[i].y - mu)*rstd*sg[col+1] + sb[col+1]);
            float y2 = gelu_exact((h4[i].z - mu)*rstd*sg[col+2] + sb[col+2]);
            float y3 = gelu_exact((h4[i].w - mu)*rstd*sg[col+3] + sb[col+3]);
            yp[2*i]   = pk2(y0, y1);
            yp[2*i+1] = pk2(y2, y3);
        }
        float wk = ws[k];
        #pragma unroll
        for (int m=0;m<Mc;m++){
            const float4* wm = reinterpret_cast<const float4*>(&sW[m*512]);
            ull a2 = 0ull;
            #pragma unroll
            for (int i=0;i<4;i++){
                float4 c4 = wm[32*i + lane];
                ffma2(a2, yp[2*i],   pk2(c4.x, c4.y));
                ffma2(a2, yp[2*i+1], pk2(c4.z, c4.w));
            }
            float lo, hi; upk2(a2, lo, hi);
            accL[m] += wk*(lo + hi);
        }
    }
    #pragma unroll
    for (int m=0;m<Mc;m++){
        float a = accL[m];
        #pragma unroll
        for (int o=16;o;o>>=1) a += __shfl_xor_sync(0xffffffffu, a, o);
        if (lane == 0) sacc[wid*Mc + m] = a;
    }
    __syncthreads();
    if (t < Mc){
        float a = 0.f;
        #pragma unroll
        for (int w2i=0;w2i<Mc;w2i++) a += sacc[w2i*Mc + t];
        g_Qp[(size_t)rn*Mc + t] = a + b2[t]*wsum;
    }
}

// ---------- top-51 + normalize + output ----------
__global__ void topk_kernel(const float* __restrict__ F, const float* __restrict__ T,
                            float* __restrict__ out){
    int r = blockIdx.x;
    int m = blockIdx.y;
    int t = threadIdx.x;
    __shared__ uint hist[256];
    __shared__ uint sh_pref, sh_rem;
    __shared__ uint wsum[4];
    __shared__ uint wtot[4];
    __shared__ float sred[4];

    float Qp = g_Qp[(size_t)r*Mc + m];
    float4 F4 = reinterpret_cast<const float4*>(&F[(size_t)r*512])[t];
    float4 T4 = reinterpret_cast<const float4*>(&T[(size_t)m*512])[t];
    float q0=F4.x*T4.x, q1=F4.y*T4.y, q2=F4.z*T4.z, q3=F4.w*T4.w;
    uint k0=__float_as_uint(fabsf(q0)), k1=__float_as_uint(fabsf(q1));
    uint k2=__float_as_uint(fabsf(q2)), k3=__float_as_uint(fabsf(q3));

    uint lane = t & 31, wid = t >> 5;
    uint pref = 0, hmask = 0, rem = KKEEP;
    for (int bp=3; bp>=0; bp--){
        hist[t] = 0; hist[t+128] = 0;
        __syncthreads();
        uint bm = hmask, p = pref;
        if ((k0 & bm) == p) atomicAdd(&hist[(k0 >> (bp*8)) & 255u], 1u);
        if ((k1 & bm) == p) atomicAdd(&hist[(k1 >> (bp*8)) & 255u], 1u);
        if ((k2 & bm) == p) atomicAdd(&hist[(k2 >> (bp*8)) & 255u], 1u);
        if ((k3 & bm) == p) atomicAdd(&hist[(k3 >> (bp*8)) & 255u], 1u);
        __syncthreads();
        uint h_lo = hist[2*t], h_hi = hist[2*t+1];
        uint pairv = h_lo + h_hi;
        uint v = pairv;
        #pragma unroll
        for (int o=1;o<32;o<<=1){
            uint u = __shfl_down_sync(0xffffffffu, v, o);
            if (lane < 32-o) v += u;
        }
        if (lane == 0) wtot[wid] = v;
        __syncthreads();
        uint tail = 0;
        for (uint wq = wid+1; wq < 4; wq++) tail += wtot[wq];
        uint Spair = v + tail;
        uint S0 = Spair;
        uint S1 = Spair - h_lo;
        uint S2 = Spair - pairv;
        if (S1 >= rem && S2 < rem){
            sh_pref = pref | ((uint)(2*t+1) << (bp*8));
            sh_rem = rem - S2;
        }
        if (S0 >= rem && S1 < rem){
            sh_pref = pref | ((uint)(2*t) << (bp*8));
            sh_rem = rem - S1;
        }
        __syncthreads();
        pref = sh_pref; rem = sh_rem;
        hmask |= (255u << (bp*8));
        __syncthreads();
    }
    uint thr = pref, req = rem;

    uint e0 = (k0==thr), e1 = (k1==thr), e2 = (k2==thr), e3 = (k3==thr);
    uint tc = e0+e1+e2+e3;
    uint inc = tc;
    #pragma unroll
    for (int o=1;o<32;o<<=1){
        uint v = __shfl_up_sync(0xffffffffu, inc, o);
        if (lane >= o) inc += v;
    }
    if (lane == 31) wsum[wid] = inc;
    __syncthreads();
    uint woff = 0;
    for (uint i=0;i<wid;i++) woff += wsum[i];
    uint p0 = woff + inc - tc;
    uint p1 = p0 + e0, p2 = p1 + e1, p3 = p2 + e2;
    bool s0 = (k0 > thr) || (e0 && p0 < req);
    bool s1 = (k1 > thr) || (e1 && p1 < req);
    bool s2 = (k2 > thr) || (e2 && p2 < req);
    bool s3 = (k3 > thr) || (e3 && p3 < req);

    float v0 = Qp*q0, v1 = Qp*q1, v2 = Qp*q2, v3 = Qp*q3;
    float ss = (s0?v0*v0:0.f) + (s1?v1*v1:0.f) + (s2?v2*v2:0.f) + (s3?v3*v3:0.f);
    #pragma unroll
    for (int o=16;o;o>>=1) ss += __shfl_xor_sync(0xffffffffu, ss, o);
    if (lane == 0) sred[wid] = ss;
    __syncthreads();
    float tot = sred[0]+sred[1]+sred[2]+sred[3];
    float nrm = fmaxf(sqrtf(tot), 1e-6f);
    float invn = 1.0f / nrm;

    size_t base = ((size_t)r*512 + (size_t)t*4)*Mc + m;
    out[base       ] = s0 ? v0*invn : 0.f;
    out[base +   Mc] = s1 ? v1*invn : 0.f;
    out[base + 2*Mc] = s2 ? v2*invn : 0.f;
    out[base + 3*Mc] = s3 ? v3*invn : 0.f;
}

// ---------- launch ----------
extern "C" void kernel_launch(void* const* d_in, const int* in_sizes, int n_in,
                              void* d_out, int out_size){
    const float* F    = (const float*)d_in[0];
    const float* text = (const float*)d_in[1];
    const float* ipw  = (const float*)d_in[2];
    const float* ipb  = (const float*)d_in[3];
    const float* outw = (const float*)d_in[4];
    const float* outb = (const float*)d_in[5];
    const float* ln1g = (const float*)d_in[6];
    const float* ln1b = (const float*)d_in[7];
    const float* ln2g = (const float*)d_in[8];
    const float* ln2b = (const float*)d_in[9];
    const float* w1   = (const float*)d_in[10];
    const float* b1   = (const float*)d_in[11];
    const float* mlng = (const float*)d_in[12];
    const float* mlnb = (const float*)d_in[13];
    const float* w2   = (const float*)d_in[14];
    const float* b2   = (const float*)d_in[15];
    const float* tmpl = (const float*)d_in[16];
    float* out = (float*)d_out;

    float *p_ctx, *p_A;
    cudaGetSymbolAddress((void**)&p_ctx, g_ctx);
    cudaGetSymbolAddress((void**)&p_A,   g_A);

    cudaFuncSetAttribute(gemm_big, cudaFuncAttributeMaxDynamicSharedMemorySize, GMM_SMEM);

    ln1_fused<<<Kc + Rr, 128>>>(text, F, ln1g, ln1b);

    sgemm_qkv<<<dim3(4,13,3), 256>>>(F, ipw, ipb);

    attn_kernel<<<dim3(Kc, Hc, Bc), 256>>>();
    aw_kernel<<<dim3(Kc, Bc), 224>>>(out + QS_ELEMS);

    sgemm_nt<<<dim3(4,5), 256>>>(p_ctx, outw, outb, p_A, Bc*Kc);
    ln_kernel<<<Bc*Kc, 128>>>(p_A, p_A, ln2g, ln2b);

    sbar_kernel<<<Rr, 128>>>();

    gemm_big<<<dim3(4, (RT + 127)/128), 256, GMM_SMEM>>>(F, w1, b1);

    h2qp<<<Rr, 640>>>(w2, b2, mlng, mlnb);

    topk_kernel<<<dim3(Rr, Mc), 128>>>(F, tmpl, out);
}